// round 14
// baseline (speedup 1.0000x reference)
#include <cuda_runtime.h>
#include <cuda_bf16.h>
#include <cstdint>

#define L_IN  1024
#define L_ENC 1024
#define BATCH 16
#define D     512
#define ROWS  (L_IN * BATCH)   // 16384

#define TM 128
#define TN 128
#define BK 8

typedef unsigned long long u64;

// Scratch (device globals)
__device__ float g_dvals[ROWS * D];                      // [b][l][e]
__device__ float g_scores[(size_t)BATCH * L_IN * L_ENC]; // [b][l][m]
__device__ float g_ctx[ROWS * D];                        // [b][l][e]
__device__ float g_R[BATCH * L_IN];                      // [b*1024+l]
// Pre-split tf32 hi/lo operands (bit patterns)
__device__ uint32_t g_ench[(size_t)L_ENC * BATCH * D];   // enc hi (same linear layout)
__device__ uint32_t g_encl[(size_t)L_ENC * BATCH * D];   // enc lo
__device__ uint32_t g_w3h[D * D];                        // W3 hi
__device__ uint32_t g_w3l[D * D];                        // W3 lo

// ---------------------------------------------------------------------------
// Packed f32x2 helpers (frozen path; lanes are IEEE fp32 RN FMAs)
// ---------------------------------------------------------------------------
__device__ __forceinline__ u64 fma2(u64 a, u64 b, u64 c) {
    u64 d;
    asm("fma.rn.f32x2 %0, %1, %2, %3;" : "=l"(d) : "l"(a), "l"(b), "l"(c));
    return d;
}
__device__ __forceinline__ u64 pack2(float x) {
    u64 d;
    asm("mov.b64 %0, {%1, %1};" : "=l"(d) : "f"(x));
    return d;
}
__device__ __forceinline__ float2 unpack2(u64 v) {
    float2 r;
    asm("mov.b64 {%0, %1}, %2;" : "=f"(r.x), "=f"(r.y) : "l"(v));
    return r;
}

#define GEMM_INNER2(As, Bs, acc2)                                            \
    _Pragma("unroll")                                                        \
    for (int kk = 0; kk < BK; ++kk) {                                        \
        float a[8];                                                          \
        *reinterpret_cast<float4*>(&a[0]) = *reinterpret_cast<const float4*>(&As[kk][4 * ty]);      \
        *reinterpret_cast<float4*>(&a[4]) = *reinterpret_cast<const float4*>(&As[kk][64 + 4 * ty]); \
        u64 bp[4];                                                           \
        *reinterpret_cast<ulonglong2*>(&bp[0]) = *reinterpret_cast<const ulonglong2*>(&Bs[kk][4 * tx]);      \
        *reinterpret_cast<ulonglong2*>(&bp[2]) = *reinterpret_cast<const ulonglong2*>(&Bs[kk][64 + 4 * tx]); \
        _Pragma("unroll")                                                    \
        for (int i = 0; i < 8; ++i) {                                        \
            const u64 ad = pack2(a[i]);                                      \
            _Pragma("unroll")                                                \
            for (int jp = 0; jp < 4; ++jp)                                   \
                acc2[i][jp] = fma2(ad, bp[jp], acc2[i][jp]);                 \
        }                                                                    \
    }

// ---------------------------------------------------------------------------
// FROZEN: K1a proj1
// ---------------------------------------------------------------------------
__global__ __launch_bounds__(256) void k_proj1(
    const float* __restrict__ A, const float* __restrict__ W,
    const float* __restrict__ bias)
{
    __shared__ __align__(16) float As[BK][TM], Bs[BK][TN];
    const int tid = threadIdx.x;
    const int tx = tid & 15, ty = tid >> 4;
    const int row0 = blockIdx.y * TM;
    const int col0 = blockIdx.x * TN;
    const int lr = tid >> 1;
    const int lk = (tid & 1) * 4;

    u64 acc2[8][4] = {};

    for (int k0 = 0; k0 < D; k0 += BK) {
        float4 a = *reinterpret_cast<const float4*>(&A[(size_t)(row0 + lr) * D + k0 + lk]);
        float4 w = *reinterpret_cast<const float4*>(&W[(size_t)(col0 + lr) * D + k0 + lk]);
        __syncthreads();
        As[lk + 0][lr] = a.x; As[lk + 1][lr] = a.y; As[lk + 2][lr] = a.z; As[lk + 3][lr] = a.w;
        Bs[lk + 0][lr] = w.x; Bs[lk + 1][lr] = w.y; Bs[lk + 2][lr] = w.z; Bs[lk + 3][lr] = w.w;
        __syncthreads();
        GEMM_INNER2(As, Bs, acc2)
    }
#pragma unroll
    for (int half = 0; half < 2; ++half) {
        const int cbase = col0 + 64 * half + 4 * tx;
        const float4 bb = *reinterpret_cast<const float4*>(&bias[cbase]);
        const float bv[4] = {bb.x, bb.y, bb.z, bb.w};
#pragma unroll
        for (int i = 0; i < 8; ++i) {
            const int r = row0 + (i < 4 ? 4 * ty + i : 64 + 4 * ty + (i - 4));
            const int b = r & 15, l = r >> 4;
            const float2 c01 = unpack2(acc2[i][2 * half]);
            const float2 c23 = unpack2(acc2[i][2 * half + 1]);
            float4 v;
            v.x = c01.x + bv[0];
            v.y = c01.y + bv[1];
            v.z = c23.x + bv[2];
            v.w = c23.y + bv[3];
            *reinterpret_cast<float4*>(&g_dvals[((size_t)b * L_IN + l) * D + cbase]) = v;
        }
    }
}

// ---------------------------------------------------------------------------
// FROZEN: K1b proj2
// ---------------------------------------------------------------------------
__global__ __launch_bounds__(256) void k_proj2(
    const float* __restrict__ A, const float* __restrict__ W,
    const float* __restrict__ bias)
{
    __shared__ __align__(16) float As[BK][TM], Bs[BK][TN];
    const int tid = threadIdx.x;
    const int tx = tid & 15, ty = tid >> 4;
    const int row0 = blockIdx.y * TM;
    const int col0 = blockIdx.x * TN;
    const int lr = tid >> 1;
    const int lk = (tid & 1) * 4;

    u64 acc2[8][4] = {};

    for (int k0 = 0; k0 < D; k0 += BK) {
        float4 a = *reinterpret_cast<const float4*>(&A[(size_t)(row0 + lr) * D + k0 + lk]);
        float4 w = *reinterpret_cast<const float4*>(&W[(size_t)(col0 + lr) * D + k0 + lk]);
        __syncthreads();
        As[lk + 0][lr] = a.x; As[lk + 1][lr] = a.y; As[lk + 2][lr] = a.z; As[lk + 3][lr] = a.w;
        Bs[lk + 0][lr] = w.x; Bs[lk + 1][lr] = w.y; Bs[lk + 2][lr] = w.z; Bs[lk + 3][lr] = w.w;
        __syncthreads();
        GEMM_INNER2(As, Bs, acc2)
    }
#pragma unroll
    for (int half = 0; half < 2; ++half) {
        const int cbase = col0 + 64 * half + 4 * tx;
        const float4 bb = *reinterpret_cast<const float4*>(&bias[cbase]);
        const float bv[4] = {bb.x, bb.y, bb.z, bb.w};
#pragma unroll
        for (int i = 0; i < 8; ++i) {
            const int r = row0 + (i < 4 ? 4 * ty + i : 64 + 4 * ty + (i - 4));
            const int b = r & 15, l = r >> 4;
            float* dst = &g_dvals[((size_t)b * L_IN + l) * D + cbase];
            float4 prev = *reinterpret_cast<const float4*>(dst);
            const float2 c01 = unpack2(acc2[i][2 * half]);
            const float2 c23 = unpack2(acc2[i][2 * half + 1]);
            float4 v;
            v.x = prev.x + (c01.x + bv[0]);
            v.y = prev.y + (c01.y + bv[1]);
            v.z = prev.z + (c23.x + bv[2]);
            v.w = prev.w + (c23.y + bv[3]);
            *reinterpret_cast<float4*>(dst) = v;
        }
    }
}

// ---------------------------------------------------------------------------
// FROZEN: K2 scores
// ---------------------------------------------------------------------------
__global__ __launch_bounds__(256) void k_scores(const float* __restrict__ enc)
{
    __shared__ __align__(16) float As[BK][TM], Bs[BK][TN];
    const int tid = threadIdx.x;
    const int tx = tid & 15, ty = tid >> 4;
    const int l0 = blockIdx.y * TM;
    const int m0 = blockIdx.x * TN;
    const int b  = blockIdx.z;
    const int lr = tid >> 1;
    const int lk = (tid & 1) * 4;

    u64 acc2[8][4] = {};

    for (int k0 = 0; k0 < D; k0 += BK) {
        float4 a = *reinterpret_cast<const float4*>(
            &g_dvals[((size_t)b * L_IN + l0 + lr) * D + k0 + lk]);
        float4 e = *reinterpret_cast<const float4*>(
            &enc[((size_t)(m0 + lr) * BATCH + b) * D + k0 + lk]);
        __syncthreads();
        As[lk + 0][lr] = a.x; As[lk + 1][lr] = a.y; As[lk + 2][lr] = a.z; As[lk + 3][lr] = a.w;
        Bs[lk + 0][lr] = e.x; Bs[lk + 1][lr] = e.y; Bs[lk + 2][lr] = e.z; Bs[lk + 3][lr] = e.w;
        __syncthreads();
        GEMM_INNER2(As, Bs, acc2)
    }
#pragma unroll
    for (int i = 0; i < 8; ++i) {
        const int l = l0 + (i < 4 ? 4 * ty + i : 64 + 4 * ty + (i - 4));
        float* base = &g_scores[((size_t)b * L_IN + l) * L_ENC + m0];
        const float2 p0 = unpack2(acc2[i][0]);
        const float2 p1 = unpack2(acc2[i][1]);
        const float2 p2 = unpack2(acc2[i][2]);
        const float2 p3 = unpack2(acc2[i][3]);
        float4 v0 = {p0.x, p0.y, p1.x, p1.y};
        float4 v1 = {p2.x, p2.y, p3.x, p3.y};
        *reinterpret_cast<float4*>(base + 4 * tx) = v0;
        *reinterpret_cast<float4*>(base + 64 + 4 * tx) = v1;
    }
}

// ---------------------------------------------------------------------------
// FROZEN: K3 rowsum — XLA row-reduce emulation
// ---------------------------------------------------------------------------
__global__ __launch_bounds__(512) void k_rowsum()
{
    __shared__ float warp_part[16];
    const int tid = threadIdx.x;
    const int row0 = blockIdx.x * 8;
    const int j = tid >> 6;
    const int t = tid & 63;
    const float* sr = g_scores + (size_t)(row0 + j) * L_ENC;
    float a = 0.f;
#pragma unroll
    for (int i = 0; i < 16; ++i)
        a += sr[t + (i << 6)];
#pragma unroll
    for (int o = 16; o; o >>= 1)
        a += __shfl_down_sync(0xFFFFFFFFu, a, o);
    if ((t & 31) == 0)
        warp_part[tid >> 5] = a;
    __syncthreads();
    if (tid < 8)
        g_R[row0 + tid] = warp_part[2 * tid] + warp_part[2 * tid + 1];
}

// ---------------------------------------------------------------------------
// TF32 split helpers + pre-split kernels
// ---------------------------------------------------------------------------
__device__ __forceinline__ void tf32_split(float x, uint32_t& hi, uint32_t& lo) {
    uint32_t h;
    asm("cvt.rna.tf32.f32 %0, %1;" : "=r"(h) : "f"(x));
    const float r = x - __uint_as_float(h);
    asm("cvt.rna.tf32.f32 %0, %1;" : "=r"(lo) : "f"(r));
    hi = h;
}

__global__ void k_split(const float* __restrict__ src,
                        uint32_t* __restrict__ h, uint32_t* __restrict__ l,
                        int n)
{
    const int i = blockIdx.x * blockDim.x + threadIdx.x;
    if (i < n) {
        uint32_t hh, ll;
        tf32_split(src[i], hh, ll);
        h[i] = hh; l[i] = ll;
    }
}

__device__ __forceinline__ void mma_tf32(float* c, const uint32_t* a, const uint32_t* b) {
    asm volatile(
        "mma.sync.aligned.m16n8k8.row.col.f32.tf32.tf32.f32 "
        "{%0,%1,%2,%3}, {%4,%5,%6,%7}, {%8,%9}, {%0,%1,%2,%3};"
        : "+f"(c[0]), "+f"(c[1]), "+f"(c[2]), "+f"(c[3])
        : "r"(a[0]), "r"(a[1]), "r"(a[2]), "r"(a[3]), "r"(b[0]), "r"(b[1]));
}

#define TC_COMPUTE(Ah, Al, Bh, Bl, acc)                                       \
    _Pragma("unroll")                                                         \
    for (int ks = 0; ks < 2; ++ks) {                                          \
        const int k8 = ks * 8;                                                \
        uint32_t ah[4][4], al[4][4], bh[4][2], bl[4][2];                      \
        _Pragma("unroll")                                                     \
        for (int mt = 0; mt < 4; ++mt) {                                      \
            const int mb = wy * 64 + mt * 16;                                 \
            ah[mt][0] = Ah[k8 + fc][mb + fr];     al[mt][0] = Al[k8 + fc][mb + fr];          \
            ah[mt][1] = Ah[k8 + fc][mb + fr + 8]; al[mt][1] = Al[k8 + fc][mb + fr + 8];      \
            ah[mt][2] = Ah[k8 + fc + 4][mb + fr];     al[mt][2] = Al[k8 + fc + 4][mb + fr];  \
            ah[mt][3] = Ah[k8 + fc + 4][mb + fr + 8]; al[mt][3] = Al[k8 + fc + 4][mb + fr + 8]; \
        }                                                                     \
        _Pragma("unroll")                                                     \
        for (int nt = 0; nt < 4; ++nt) {                                      \
            const int nb = wx * 32 + nt * 8;                                  \
            bh[nt][0] = Bh[k8 + fc][nb + fr];     bl[nt][0] = Bl[k8 + fc][nb + fr];          \
            bh[nt][1] = Bh[k8 + fc + 4][nb + fr]; bl[nt][1] = Bl[k8 + fc + 4][nb + fr];      \
        }                                                                     \
        _Pragma("unroll")                                                     \
        for (int mt = 0; mt < 4; ++mt)                                        \
            _Pragma("unroll")                                                 \
            for (int nt = 0; nt < 4; ++nt) {                                  \
                mma_tf32(acc[mt][nt], ah[mt], bl[nt]);                        \
                mma_tf32(acc[mt][nt], al[mt], bh[nt]);                        \
                mma_tf32(acc[mt][nt], ah[mt], bh[nt]);                        \
            }                                                                 \
    }

// ---------------------------------------------------------------------------
// K4tc: ctx — B (enc) pre-split loads, register-prefetch pipeline
// ---------------------------------------------------------------------------
__global__ __launch_bounds__(256) void k_ctx_tc()
{
    __shared__ uint32_t Ah[16][132], Al[16][132], Bh[16][132], Bl[16][132];
    const int tid  = threadIdx.x;
    const int lane = tid & 31, warp = tid >> 5;
    const int wy = warp & 1, wx = warp >> 1;
    const int e0 = blockIdx.x * 128;
    const int l0 = blockIdx.y * 128;
    const int b  = blockIdx.z;
    const int fr = lane >> 2, fc = lane & 3;

    const int ar  = tid >> 2;            // A stage row 0..63 (and +64)
    const int akc = (tid & 3) * 4;       // A stage k offset
    const int bkr = tid >> 4;            // B stage k row 0..15
    const int bec = (tid & 15) * 8;      // B stage col offset

    const float inv0 = __fdiv_rn(1.f, g_R[b * L_IN + l0 + ar]);
    const float inv1 = __fdiv_rn(1.f, g_R[b * L_IN + l0 + ar + 64]);

    const size_t aoff0 = ((size_t)b * L_IN + l0 + ar) * L_ENC + akc;
    const size_t aoff1 = ((size_t)b * L_IN + l0 + ar + 64) * L_ENC + akc;
    const size_t boff  = ((size_t)bkr * BATCH + b) * D + e0 + bec;
    const size_t bstep = (size_t)16 * BATCH * D;

    float acc[4][4][4] = {};

    // prefetch k0 = 0
    float4 sa0 = *reinterpret_cast<const float4*>(&g_scores[aoff0]);
    float4 sa1 = *reinterpret_cast<const float4*>(&g_scores[aoff1]);
    uint4  vh0 = *reinterpret_cast<const uint4*>(&g_ench[boff]);
    uint4  vh1 = *reinterpret_cast<const uint4*>(&g_ench[boff + 4]);
    uint4  vl0 = *reinterpret_cast<const uint4*>(&g_encl[boff]);
    uint4  vl1 = *reinterpret_cast<const uint4*>(&g_encl[boff + 4]);

    for (int k0 = 0; k0 < L_ENC; k0 += 16) {
        __syncthreads();
        {
            float v0[4] = {sa0.x * inv0, sa0.y * inv0, sa0.z * inv0, sa0.w * inv0};
            float v1[4] = {sa1.x * inv1, sa1.y * inv1, sa1.z * inv1, sa1.w * inv1};
#pragma unroll
            for (int j = 0; j < 4; ++j) {
                uint32_t h, l;
                tf32_split(v0[j], h, l); Ah[akc + j][ar] = h;      Al[akc + j][ar] = l;
                tf32_split(v1[j], h, l); Ah[akc + j][ar + 64] = h; Al[akc + j][ar + 64] = l;
            }
            *reinterpret_cast<uint4*>(&Bh[bkr][bec])     = vh0;
            *reinterpret_cast<uint4*>(&Bh[bkr][bec + 4]) = vh1;
            *reinterpret_cast<uint4*>(&Bl[bkr][bec])     = vl0;
            *reinterpret_cast<uint4*>(&Bl[bkr][bec + 4]) = vl1;
        }
        __syncthreads();
        if (k0 + 16 < L_ENC) {
            const int kn = k0 + 16;
            sa0 = *reinterpret_cast<const float4*>(&g_scores[aoff0 + kn]);
            sa1 = *reinterpret_cast<const float4*>(&g_scores[aoff1 + kn]);
            const size_t bo = boff + (size_t)(kn >> 4) * bstep;
            vh0 = *reinterpret_cast<const uint4*>(&g_ench[bo]);
            vh1 = *reinterpret_cast<const uint4*>(&g_ench[bo + 4]);
            vl0 = *reinterpret_cast<const uint4*>(&g_encl[bo]);
            vl1 = *reinterpret_cast<const uint4*>(&g_encl[bo + 4]);
        }
        TC_COMPUTE(Ah, Al, Bh, Bl, acc)
    }
#pragma unroll
    for (int mt = 0; mt < 4; ++mt)
#pragma unroll
        for (int nt = 0; nt < 4; ++nt) {
            const int row = l0 + wy * 64 + mt * 16 + fr;
            const int col = e0 + wx * 32 + nt * 8 + 2 * fc;
            float2 v0 = {acc[mt][nt][0], acc[mt][nt][1]};
            float2 v1 = {acc[mt][nt][2], acc[mt][nt][3]};
            *reinterpret_cast<float2*>(&g_ctx[((size_t)b * L_IN + row) * D + col]) = v0;
            *reinterpret_cast<float2*>(&g_ctx[((size_t)b * L_IN + row + 8) * D + col]) = v1;
        }
}

// ---------------------------------------------------------------------------
// K5tc: out — B (W3) pre-split loads, register-prefetch pipeline
// ---------------------------------------------------------------------------
__global__ __launch_bounds__(256) void k_out_tc(
    const float* __restrict__ b3, float* __restrict__ out)
{
    __shared__ uint32_t Ah[16][132], Al[16][132], Bh[16][132], Bl[16][132];
    const int tid  = threadIdx.x;
    const int lane = tid & 31, warp = tid >> 5;
    const int wy = warp & 1, wx = warp >> 1;
    const int col0 = blockIdx.x * 128;
    const int row0 = blockIdx.y * 128;   // rows r = b*1024 + l (g_ctx order)
    const int fr = lane >> 2, fc = lane & 3;

    const int ar  = tid >> 2;
    const int akc = (tid & 3) * 4;
    const int bnr = tid >> 1;            // B stage n row 0..127
    const int bkc = (tid & 1) * 8;       // B stage k offset

    const size_t aoff0 = (size_t)(row0 + ar) * D + akc;
    const size_t aoff1 = (size_t)(row0 + ar + 64) * D + akc;
    const size_t boff  = (size_t)(col0 + bnr) * D + bkc;

    float acc[4][4][4] = {};

    float4 a0 = *reinterpret_cast<const float4*>(&g_ctx[aoff0]);
    float4 a1 = *reinterpret_cast<const float4*>(&g_ctx[aoff1]);
    uint4  wh0 = *reinterpret_cast<const uint4*>(&g_w3h[boff]);
    uint4  wh1 = *reinterpret_cast<const uint4*>(&g_w3h[boff + 4]);
    uint4  wl0 = *reinterpret_cast<const uint4*>(&g_w3l[boff]);
    uint4  wl1 = *reinterpret_cast<const uint4*>(&g_w3l[boff + 4]);

    for (int k0 = 0; k0 < D; k0 += 16) {
        __syncthreads();
        {
            const float va0[4] = {a0.x, a0.y, a0.z, a0.w};
            const float va1[4] = {a1.x, a1.y, a1.z, a1.w};
#pragma unroll
            for (int j = 0; j < 4; ++j) {
                uint32_t h, l;
                tf32_split(va0[j], h, l); Ah[akc + j][ar] = h;      Al[akc + j][ar] = l;
                tf32_split(va1[j], h, l); Ah[akc + j][ar + 64] = h; Al[akc + j][ar + 64] = l;
            }
            // W3 rows: Bh[k][n] layout — scatter 8 k's of one n (bkc..bkc+7)
            const uint32_t wh[8] = {wh0.x, wh0.y, wh0.z, wh0.w, wh1.x, wh1.y, wh1.z, wh1.w};
            const uint32_t wl[8] = {wl0.x, wl0.y, wl0.z, wl0.w, wl1.x, wl1.y, wl1.z, wl1.w};
#pragma unroll
            for (int j = 0; j < 8; ++j) {
                Bh[bkc + j][bnr] = wh[j];
                Bl[bkc + j][bnr] = wl[j];
            }
        }
        __syncthreads();
        if (k0 + 16 < D) {
            const int kn = k0 + 16;
            a0 = *reinterpret_cast<const float4*>(&g_ctx[aoff0 + kn]);
            a1 = *reinterpret_cast<const float4*>(&g_ctx[aoff1 + kn]);
            wh0 = *reinterpret_cast<const uint4*>(&g_w3h[boff + kn]);
            wh1 = *reinterpret_cast<const uint4*>(&g_w3h[boff + kn + 4]);
            wl0 = *reinterpret_cast<const uint4*>(&g_w3l[boff + kn]);
            wl1 = *reinterpret_cast<const uint4*>(&g_w3l[boff + kn + 4]);
        }
        TC_COMPUTE(Ah, Al, Bh, Bl, acc)
    }
#pragma unroll
    for (int mt = 0; mt < 4; ++mt)
#pragma unroll
        for (int nt = 0; nt < 4; ++nt) {
            const int col = col0 + wx * 32 + nt * 8 + 2 * fc;
            const float bx = b3[col], by = b3[col + 1];
#pragma unroll
            for (int h = 0; h < 2; ++h) {
                const int r = row0 + wy * 64 + mt * 16 + fr + 8 * h;
                const int b = r >> 10, l = r & (L_IN - 1);
                float2 v = {acc[mt][nt][2 * h] + bx, acc[mt][nt][2 * h + 1] + by};
                *reinterpret_cast<float2*>(&out[((size_t)l * BATCH + b) * D + col]) = v;
            }
        }
}

// ---------------------------------------------------------------------------
extern "C" void kernel_launch(void* const* d_in, const int* in_sizes, int n_in,
                              void* d_out, int out_size)
{
    const float* in_seq   = (const float*)d_in[0];
    const float* enc_seq  = (const float*)d_in[1];
    const float* prev_tgt = (const float*)d_in[2];
    const float* W_in2enc = (const float*)d_in[3];
    const float* b_in2enc = (const float*)d_in[4];
    const float* W_lab2enc= (const float*)d_in[5];
    const float* b_lab2enc= (const float*)d_in[6];
    const float* W_enc2in = (const float*)d_in[7];
    const float* b_enc2in = (const float*)d_in[8];
    float* out = (float*)d_out;

    uint32_t *ench, *encl, *w3h, *w3l;
    cudaGetSymbolAddress((void**)&ench, g_ench);
    cudaGetSymbolAddress((void**)&encl, g_encl);
    cudaGetSymbolAddress((void**)&w3h,  g_w3h);
    cudaGetSymbolAddress((void**)&w3l,  g_w3l);

    const int n_enc = L_ENC * BATCH * D;
    k_split<<<(n_enc + 255) / 256, 256>>>(enc_seq, ench, encl, n_enc);
    k_split<<<(D * D + 255) / 256, 256>>>(W_enc2in, w3h, w3l, D * D);

    k_proj1  <<<dim3(D / TN, ROWS / TM), 256>>>(in_seq,   W_in2enc,  b_in2enc);
    k_proj2  <<<dim3(D / TN, ROWS / TM), 256>>>(prev_tgt, W_lab2enc, b_lab2enc);
    k_scores <<<dim3(L_ENC / TN, L_IN / TM, BATCH), 256>>>(enc_seq);
    k_rowsum <<<BATCH * L_IN / 8, 512>>>();
    k_ctx_tc <<<dim3(D / 128, L_IN / 128, BATCH), 256>>>();
    k_out_tc <<<dim3(D / 128, ROWS / 128), 256>>>(b_enc2in, out);
}

// round 15
// speedup vs baseline: 1.1697x; 1.1697x over previous
#include <cuda_runtime.h>
#include <cuda_bf16.h>
#include <cstdint>

#define L_IN  1024
#define L_ENC 1024
#define BATCH 16
#define D     512
#define ROWS  (L_IN * BATCH)   // 16384

#define TM 128
#define TN 128
#define BK 8

typedef unsigned long long u64;

// Scratch (device globals)
__device__ float g_dvals[ROWS * D];                      // [b][l][e]
__device__ float g_scores[(size_t)BATCH * L_IN * L_ENC]; // [b][l][m]
__device__ float g_ctx[ROWS * D];                        // [b][l][e]
__device__ float g_R[BATCH * L_IN];                      // [b*1024+l]

// ---------------------------------------------------------------------------
// Packed f32x2 helpers (frozen path; lanes are IEEE fp32 RN FMAs)
// ---------------------------------------------------------------------------
__device__ __forceinline__ u64 fma2(u64 a, u64 b, u64 c) {
    u64 d;
    asm("fma.rn.f32x2 %0, %1, %2, %3;" : "=l"(d) : "l"(a), "l"(b), "l"(c));
    return d;
}
__device__ __forceinline__ u64 pack2(float x) {
    u64 d;
    asm("mov.b64 %0, {%1, %1};" : "=l"(d) : "f"(x));
    return d;
}
__device__ __forceinline__ float2 unpack2(u64 v) {
    float2 r;
    asm("mov.b64 {%0, %1}, %2;" : "=f"(r.x), "=f"(r.y) : "l"(v));
    return r;
}

#define GEMM_INNER2(As, Bs, acc2)                                            \
    _Pragma("unroll")                                                        \
    for (int kk = 0; kk < BK; ++kk) {                                        \
        float a[8];                                                          \
        *reinterpret_cast<float4*>(&a[0]) = *reinterpret_cast<const float4*>(&As[kk][4 * ty]);      \
        *reinterpret_cast<float4*>(&a[4]) = *reinterpret_cast<const float4*>(&As[kk][64 + 4 * ty]); \
        u64 bp[4];                                                           \
        *reinterpret_cast<ulonglong2*>(&bp[0]) = *reinterpret_cast<const ulonglong2*>(&Bs[kk][4 * tx]);      \
        *reinterpret_cast<ulonglong2*>(&bp[2]) = *reinterpret_cast<const ulonglong2*>(&Bs[kk][64 + 4 * tx]); \
        _Pragma("unroll")                                                    \
        for (int i = 0; i < 8; ++i) {                                        \
            const u64 ad = pack2(a[i]);                                      \
            _Pragma("unroll")                                                \
            for (int jp = 0; jp < 4; ++jp)                                   \
                acc2[i][jp] = fma2(ad, bp[jp], acc2[i][jp]);                 \
        }                                                                    \
    }

#define STAGE_STORE(As, Bs, a, w)                                            \
    As[lk + 0][lr] = a.x; As[lk + 1][lr] = a.y;                              \
    As[lk + 2][lr] = a.z; As[lk + 3][lr] = a.w;                              \
    Bs[lk + 0][lr] = w.x; Bs[lk + 1][lr] = w.y;                              \
    Bs[lk + 2][lr] = w.z; Bs[lk + 3][lr] = w.w;

// ---------------------------------------------------------------------------
// FROZEN arithmetic, double-buffered staging: K1a proj1
// ---------------------------------------------------------------------------
__global__ __launch_bounds__(256) void k_proj1(
    const float* __restrict__ A, const float* __restrict__ W,
    const float* __restrict__ bias)
{
    __shared__ __align__(16) float As[2][BK][TM], Bs[2][BK][TN];
    const int tid = threadIdx.x;
    const int tx = tid & 15, ty = tid >> 4;
    const int row0 = blockIdx.y * TM;
    const int col0 = blockIdx.x * TN;
    const int lr = tid >> 1;
    const int lk = (tid & 1) * 4;

    const float* Ap = &A[(size_t)(row0 + lr) * D + lk];
    const float* Wp = &W[(size_t)(col0 + lr) * D + lk];

    u64 acc2[8][4] = {};

    float4 a = *reinterpret_cast<const float4*>(Ap);
    float4 w = *reinterpret_cast<const float4*>(Wp);
    STAGE_STORE(As[0], Bs[0], a, w)
    __syncthreads();

    for (int k0 = 0; k0 < D; k0 += BK) {
        const int cur = (k0 >> 3) & 1;
        const bool more = (k0 + BK) < D;
        if (more) {
            a = *reinterpret_cast<const float4*>(Ap + k0 + BK);
            w = *reinterpret_cast<const float4*>(Wp + k0 + BK);
        }
        GEMM_INNER2(As[cur], Bs[cur], acc2)
        if (more) {
            STAGE_STORE(As[cur ^ 1], Bs[cur ^ 1], a, w)
            __syncthreads();
        }
    }
#pragma unroll
    for (int half = 0; half < 2; ++half) {
        const int cbase = col0 + 64 * half + 4 * tx;
        const float4 bb = *reinterpret_cast<const float4*>(&bias[cbase]);
        const float bv[4] = {bb.x, bb.y, bb.z, bb.w};
#pragma unroll
        for (int i = 0; i < 8; ++i) {
            const int r = row0 + (i < 4 ? 4 * ty + i : 64 + 4 * ty + (i - 4));
            const int b = r & 15, l = r >> 4;
            const float2 c01 = unpack2(acc2[i][2 * half]);
            const float2 c23 = unpack2(acc2[i][2 * half + 1]);
            float4 v;
            v.x = c01.x + bv[0];
            v.y = c01.y + bv[1];
            v.z = c23.x + bv[2];
            v.w = c23.y + bv[3];
            *reinterpret_cast<float4*>(&g_dvals[((size_t)b * L_IN + l) * D + cbase]) = v;
        }
    }
}

// ---------------------------------------------------------------------------
// FROZEN arithmetic, double-buffered staging: K1b proj2
// ---------------------------------------------------------------------------
__global__ __launch_bounds__(256) void k_proj2(
    const float* __restrict__ A, const float* __restrict__ W,
    const float* __restrict__ bias)
{
    __shared__ __align__(16) float As[2][BK][TM], Bs[2][BK][TN];
    const int tid = threadIdx.x;
    const int tx = tid & 15, ty = tid >> 4;
    const int row0 = blockIdx.y * TM;
    const int col0 = blockIdx.x * TN;
    const int lr = tid >> 1;
    const int lk = (tid & 1) * 4;

    const float* Ap = &A[(size_t)(row0 + lr) * D + lk];
    const float* Wp = &W[(size_t)(col0 + lr) * D + lk];

    u64 acc2[8][4] = {};

    float4 a = *reinterpret_cast<const float4*>(Ap);
    float4 w = *reinterpret_cast<const float4*>(Wp);
    STAGE_STORE(As[0], Bs[0], a, w)
    __syncthreads();

    for (int k0 = 0; k0 < D; k0 += BK) {
        const int cur = (k0 >> 3) & 1;
        const bool more = (k0 + BK) < D;
        if (more) {
            a = *reinterpret_cast<const float4*>(Ap + k0 + BK);
            w = *reinterpret_cast<const float4*>(Wp + k0 + BK);
        }
        GEMM_INNER2(As[cur], Bs[cur], acc2)
        if (more) {
            STAGE_STORE(As[cur ^ 1], Bs[cur ^ 1], a, w)
            __syncthreads();
        }
    }
#pragma unroll
    for (int half = 0; half < 2; ++half) {
        const int cbase = col0 + 64 * half + 4 * tx;
        const float4 bb = *reinterpret_cast<const float4*>(&bias[cbase]);
        const float bv[4] = {bb.x, bb.y, bb.z, bb.w};
#pragma unroll
        for (int i = 0; i < 8; ++i) {
            const int r = row0 + (i < 4 ? 4 * ty + i : 64 + 4 * ty + (i - 4));
            const int b = r & 15, l = r >> 4;
            float* dst = &g_dvals[((size_t)b * L_IN + l) * D + cbase];
            float4 prev = *reinterpret_cast<const float4*>(dst);
            const float2 c01 = unpack2(acc2[i][2 * half]);
            const float2 c23 = unpack2(acc2[i][2 * half + 1]);
            float4 v;
            v.x = prev.x + (c01.x + bv[0]);
            v.y = prev.y + (c01.y + bv[1]);
            v.z = prev.z + (c23.x + bv[2]);
            v.w = prev.w + (c23.y + bv[3]);
            *reinterpret_cast<float4*>(dst) = v;
        }
    }
}

// ---------------------------------------------------------------------------
// FROZEN arithmetic, double-buffered staging: K2 scores
// ---------------------------------------------------------------------------
__global__ __launch_bounds__(256) void k_scores(const float* __restrict__ enc)
{
    __shared__ __align__(16) float As[2][BK][TM], Bs[2][BK][TN];
    const int tid = threadIdx.x;
    const int tx = tid & 15, ty = tid >> 4;
    const int l0 = blockIdx.y * TM;
    const int m0 = blockIdx.x * TN;
    const int b  = blockIdx.z;
    const int lr = tid >> 1;
    const int lk = (tid & 1) * 4;

    const float* Ap = &g_dvals[((size_t)b * L_IN + l0 + lr) * D + lk];
    const float* Ep = &enc[((size_t)(m0 + lr) * BATCH + b) * D + lk];

    u64 acc2[8][4] = {};

    float4 a = *reinterpret_cast<const float4*>(Ap);
    float4 w = *reinterpret_cast<const float4*>(Ep);
    STAGE_STORE(As[0], Bs[0], a, w)
    __syncthreads();

    for (int k0 = 0; k0 < D; k0 += BK) {
        const int cur = (k0 >> 3) & 1;
        const bool more = (k0 + BK) < D;
        if (more) {
            a = *reinterpret_cast<const float4*>(Ap + k0 + BK);
            w = *reinterpret_cast<const float4*>(Ep + k0 + BK);
        }
        GEMM_INNER2(As[cur], Bs[cur], acc2)
        if (more) {
            STAGE_STORE(As[cur ^ 1], Bs[cur ^ 1], a, w)
            __syncthreads();
        }
    }
#pragma unroll
    for (int i = 0; i < 8; ++i) {
        const int l = l0 + (i < 4 ? 4 * ty + i : 64 + 4 * ty + (i - 4));
        float* base = &g_scores[((size_t)b * L_IN + l) * L_ENC + m0];
        const float2 p0 = unpack2(acc2[i][0]);
        const float2 p1 = unpack2(acc2[i][1]);
        const float2 p2 = unpack2(acc2[i][2]);
        const float2 p3 = unpack2(acc2[i][3]);
        float4 v0 = {p0.x, p0.y, p1.x, p1.y};
        float4 v1 = {p2.x, p2.y, p3.x, p3.y};
        *reinterpret_cast<float4*>(base + 4 * tx) = v0;
        *reinterpret_cast<float4*>(base + 64 + 4 * tx) = v1;
    }
}

// ---------------------------------------------------------------------------
// FROZEN: K3 rowsum — XLA row-reduce emulation (bit-identical)
// ---------------------------------------------------------------------------
__global__ __launch_bounds__(512) void k_rowsum()
{
    __shared__ float warp_part[16];
    const int tid = threadIdx.x;
    const int row0 = blockIdx.x * 8;
    const int j = tid >> 6;
    const int t = tid & 63;
    const float* sr = g_scores + (size_t)(row0 + j) * L_ENC;
    float a = 0.f;
#pragma unroll
    for (int i = 0; i < 16; ++i)
        a += sr[t + (i << 6)];
#pragma unroll
    for (int o = 16; o; o >>= 1)
        a += __shfl_down_sync(0xFFFFFFFFu, a, o);
    if ((t & 31) == 0)
        warp_part[tid >> 5] = a;
    __syncthreads();
    if (tid < 8)
        g_R[row0 + tid] = warp_part[2 * tid] + warp_part[2 * tid + 1];
}

// ---------------------------------------------------------------------------
// INSENSITIVE NUMERATOR — TF32x3 tensor-core GEMMs (reverted to R13 form)
// ---------------------------------------------------------------------------
__device__ __forceinline__ void tf32_split(float x, uint32_t& hi, uint32_t& lo) {
    uint32_t h;
    asm("cvt.rna.tf32.f32 %0, %1;" : "=r"(h) : "f"(x));
    const float r = x - __uint_as_float(h);
    asm("cvt.rna.tf32.f32 %0, %1;" : "=r"(lo) : "f"(r));
    hi = h;
}

__device__ __forceinline__ void mma_tf32(float* c, const uint32_t* a, const uint32_t* b) {
    asm volatile(
        "mma.sync.aligned.m16n8k8.row.col.f32.tf32.tf32.f32 "
        "{%0,%1,%2,%3}, {%4,%5,%6,%7}, {%8,%9}, {%0,%1,%2,%3};"
        : "+f"(c[0]), "+f"(c[1]), "+f"(c[2]), "+f"(c[3])
        : "r"(a[0]), "r"(a[1]), "r"(a[2]), "r"(a[3]), "r"(b[0]), "r"(b[1]));
}

__global__ __launch_bounds__(256) void k_ctx_tc(const float* __restrict__ enc)
{
    __shared__ uint32_t Ah[16][132], Al[16][132], Bh[16][132], Bl[16][132];
    const int tid  = threadIdx.x;
    const int lane = tid & 31, warp = tid >> 5;
    const int wy = warp & 1, wx = warp >> 1;
    const int e0 = blockIdx.x * 128;
    const int l0 = blockIdx.y * 128;
    const int b  = blockIdx.z;

    const int ar  = tid >> 2;
    const int akc = (tid & 3) * 4;
    const int bkr = tid >> 4;
    const int bec = (tid & 15) * 8;

    const float inv0 = __fdiv_rn(1.f, g_R[b * L_IN + l0 + ar]);
    const float inv1 = __fdiv_rn(1.f, g_R[b * L_IN + l0 + ar + 64]);

    float acc[4][4][4] = {};

    for (int k0 = 0; k0 < L_ENC; k0 += 16) {
        float4 sa0 = *reinterpret_cast<const float4*>(
            &g_scores[((size_t)b * L_IN + l0 + ar) * L_ENC + k0 + akc]);
        float4 sa1 = *reinterpret_cast<const float4*>(
            &g_scores[((size_t)b * L_IN + l0 + ar + 64) * L_ENC + k0 + akc]);
        float4 eb0 = *reinterpret_cast<const float4*>(
            &enc[((size_t)(k0 + bkr) * BATCH + b) * D + e0 + bec]);
        float4 eb1 = *reinterpret_cast<const float4*>(
            &enc[((size_t)(k0 + bkr) * BATCH + b) * D + e0 + bec + 4]);
        __syncthreads();
        {
            float v0[4] = {sa0.x * inv0, sa0.y * inv0, sa0.z * inv0, sa0.w * inv0};
            float v1[4] = {sa1.x * inv1, sa1.y * inv1, sa1.z * inv1, sa1.w * inv1};
#pragma unroll
            for (int j = 0; j < 4; ++j) {
                uint32_t h, l;
                tf32_split(v0[j], h, l); Ah[akc + j][ar] = h;      Al[akc + j][ar] = l;
                tf32_split(v1[j], h, l); Ah[akc + j][ar + 64] = h; Al[akc + j][ar + 64] = l;
            }
            const float w[8] = {eb0.x, eb0.y, eb0.z, eb0.w, eb1.x, eb1.y, eb1.z, eb1.w};
#pragma unroll
            for (int j = 0; j < 8; ++j) {
                uint32_t h, l;
                tf32_split(w[j], h, l); Bh[bkr][bec + j] = h; Bl[bkr][bec + j] = l;
            }
        }
        __syncthreads();
#pragma unroll
        for (int ks = 0; ks < 2; ++ks) {
            const int k8 = ks * 8;
            const int fr = lane >> 2, fc = lane & 3;
            uint32_t ah[4][4], al[4][4], bh[4][2], bl[4][2];
#pragma unroll
            for (int mt = 0; mt < 4; ++mt) {
                const int mb = wy * 64 + mt * 16;
                ah[mt][0] = Ah[k8 + fc][mb + fr];     al[mt][0] = Al[k8 + fc][mb + fr];
                ah[mt][1] = Ah[k8 + fc][mb + fr + 8]; al[mt][1] = Al[k8 + fc][mb + fr + 8];
                ah[mt][2] = Ah[k8 + fc + 4][mb + fr];     al[mt][2] = Al[k8 + fc + 4][mb + fr];
                ah[mt][3] = Ah[k8 + fc + 4][mb + fr + 8]; al[mt][3] = Al[k8 + fc + 4][mb + fr + 8];
            }
#pragma unroll
            for (int nt = 0; nt < 4; ++nt) {
                const int nb = wx * 32 + nt * 8;
                bh[nt][0] = Bh[k8 + fc][nb + fr];     bl[nt][0] = Bl[k8 + fc][nb + fr];
                bh[nt][1] = Bh[k8 + fc + 4][nb + fr]; bl[nt][1] = Bl[k8 + fc + 4][nb + fr];
            }
#pragma unroll
            for (int mt = 0; mt < 4; ++mt)
#pragma unroll
                for (int nt = 0; nt < 4; ++nt) {
                    mma_tf32(acc[mt][nt], ah[mt], bl[nt]);
                    mma_tf32(acc[mt][nt], al[mt], bh[nt]);
                    mma_tf32(acc[mt][nt], ah[mt], bh[nt]);
                }
        }
    }
    const int fr = lane >> 2, fc = lane & 3;
#pragma unroll
    for (int mt = 0; mt < 4; ++mt)
#pragma unroll
        for (int nt = 0; nt < 4; ++nt) {
            const int row = l0 + wy * 64 + mt * 16 + fr;
            const int col = e0 + wx * 32 + nt * 8 + 2 * fc;
            float2 v0 = {acc[mt][nt][0], acc[mt][nt][1]};
            float2 v1 = {acc[mt][nt][2], acc[mt][nt][3]};
            *reinterpret_cast<float2*>(&g_ctx[((size_t)b * L_IN + row) * D + col]) = v0;
            *reinterpret_cast<float2*>(&g_ctx[((size_t)b * L_IN + row + 8) * D + col]) = v1;
        }
}

__global__ __launch_bounds__(256) void k_out_tc(
    const float* __restrict__ W3, const float* __restrict__ b3,
    float* __restrict__ out)
{
    __shared__ uint32_t Ah[16][132], Al[16][132], Bh[16][132], Bl[16][132];
    const int tid  = threadIdx.x;
    const int lane = tid & 31, warp = tid >> 5;
    const int wy = warp & 1, wx = warp >> 1;
    const int col0 = blockIdx.x * 128;
    const int row0 = blockIdx.y * 128;

    const int ar  = tid >> 2;
    const int akc = (tid & 3) * 4;
    const int bnr = tid >> 1;
    const int bkc = (tid & 1) * 8;

    float acc[4][4][4] = {};

    for (int k0 = 0; k0 < D; k0 += 16) {
        float4 a0 = *reinterpret_cast<const float4*>(
            &g_ctx[(size_t)(row0 + ar) * D + k0 + akc]);
        float4 a1 = *reinterpret_cast<const float4*>(
            &g_ctx[(size_t)(row0 + ar + 64) * D + k0 + akc]);
        float4 w0 = *reinterpret_cast<const float4*>(
            &W3[(size_t)(col0 + bnr) * D + k0 + bkc]);
        float4 w1 = *reinterpret_cast<const float4*>(
            &W3[(size_t)(col0 + bnr) * D + k0 + bkc + 4]);
        __syncthreads();
        {
            const float va0[4] = {a0.x, a0.y, a0.z, a0.w};
            const float va1[4] = {a1.x, a1.y, a1.z, a1.w};
#pragma unroll
            for (int j = 0; j < 4; ++j) {
                uint32_t h, l;
                tf32_split(va0[j], h, l); Ah[akc + j][ar] = h;      Al[akc + j][ar] = l;
                tf32_split(va1[j], h, l); Ah[akc + j][ar + 64] = h; Al[akc + j][ar + 64] = l;
            }
            const float w[8] = {w0.x, w0.y, w0.z, w0.w, w1.x, w1.y, w1.z, w1.w};
#pragma unroll
            for (int j = 0; j < 8; ++j) {
                uint32_t h, l;
                tf32_split(w[j], h, l); Bh[bkc + j][bnr] = h; Bl[bkc + j][bnr] = l;
            }
        }
        __syncthreads();
#pragma unroll
        for (int ks = 0; ks < 2; ++ks) {
            const int k8 = ks * 8;
            const int fr = lane >> 2, fc = lane & 3;
            uint32_t ah[4][4], al[4][4], bh[4][2], bl[4][2];
#pragma unroll
            for (int mt = 0; mt < 4; ++mt) {
                const int mb = wy * 64 + mt * 16;
                ah[mt][0] = Ah[k8 + fc][mb + fr];     al[mt][0] = Al[k8 + fc][mb + fr];
                ah[mt][1] = Ah[k8 + fc][mb + fr + 8]; al[mt][1] = Al[k8 + fc][mb + fr + 8];
                ah[mt][2] = Ah[k8 + fc + 4][mb + fr];     al[mt][2] = Al[k8 + fc + 4][mb + fr];
                ah[mt][3] = Ah[k8 + fc + 4][mb + fr + 8]; al[mt][3] = Al[k8 + fc + 4][mb + fr + 8];
            }
#pragma unroll
            for (int nt = 0; nt < 4; ++nt) {
                const int nb = wx * 32 + nt * 8;
                bh[nt][0] = Bh[k8 + fc][nb + fr];     bl[nt][0] = Bl[k8 + fc][nb + fr];
                bh[nt][1] = Bh[k8 + fc + 4][nb + fr]; bl[nt][1] = Bl[k8 + fc + 4][nb + fr];
            }
#pragma unroll
            for (int mt = 0; mt < 4; ++mt)
#pragma unroll
                for (int nt = 0; nt < 4; ++nt) {
                    mma_tf32(acc[mt][nt], ah[mt], bl[nt]);
                    mma_tf32(acc[mt][nt], al[mt], bh[nt]);
                    mma_tf32(acc[mt][nt], ah[mt], bh[nt]);
                }
        }
    }
    const int fr = lane >> 2, fc = lane & 3;
#pragma unroll
    for (int mt = 0; mt < 4; ++mt)
#pragma unroll
        for (int nt = 0; nt < 4; ++nt) {
            const int col = col0 + wx * 32 + nt * 8 + 2 * fc;
            const float bx = b3[col], by = b3[col + 1];
#pragma unroll
            for (int h = 0; h < 2; ++h) {
                const int r = row0 + wy * 64 + mt * 16 + fr + 8 * h;
                const int b = r >> 10, l = r & (L_IN - 1);
                float2 v = {acc[mt][nt][2 * h] + bx, acc[mt][nt][2 * h + 1] + by};
                *reinterpret_cast<float2*>(&out[((size_t)l * BATCH + b) * D + col]) = v;
            }
        }
}

// ---------------------------------------------------------------------------
extern "C" void kernel_launch(void* const* d_in, const int* in_sizes, int n_in,
                              void* d_out, int out_size)
{
    const float* in_seq   = (const float*)d_in[0];
    const float* enc_seq  = (const float*)d_in[1];
    const float* prev_tgt = (const float*)d_in[2];
    const float* W_in2enc = (const float*)d_in[3];
    const float* b_in2enc = (const float*)d_in[4];
    const float* W_lab2enc= (const float*)d_in[5];
    const float* b_lab2enc= (const float*)d_in[6];
    const float* W_enc2in = (const float*)d_in[7];
    const float* b_enc2in = (const float*)d_in[8];
    float* out = (float*)d_out;

    k_proj1  <<<dim3(D / TN, ROWS / TM), 256>>>(in_seq,   W_in2enc,  b_in2enc);
    k_proj2  <<<dim3(D / TN, ROWS / TM), 256>>>(prev_tgt, W_lab2enc, b_lab2enc);
    k_scores <<<dim3(L_ENC / TN, L_IN / TM, BATCH), 256>>>(enc_seq);
    k_rowsum <<<BATCH * L_IN / 8, 512>>>();
    k_ctx_tc <<<dim3(D / 128, L_IN / 128, BATCH), 256>>>(enc_seq);
    k_out_tc <<<dim3(D / 128, ROWS / 128), 256>>>(W_enc2in, b_enc2in, out);
}